// round 13
// baseline (speedup 1.0000x reference)
#include <cuda_runtime.h>
#include <math.h>

#define DIM 64
#define MAXN 200000

// Scratch (allocation-free rule: __device__ globals). 102 MB total.
__device__ float g_bufA[(size_t)MAXN * DIM];
__device__ float g_bufB[(size_t)MAXN * DIM];
__device__ int   g_rowptr[MAXN + 1];

__device__ __forceinline__ float warpAllSum(float v) {
#pragma unroll
    for (int o = 16; o; o >>= 1) v += __shfl_xor_sync(0xffffffffu, v, o);
    return v;
}

// butterfly within a 16-lane half (offsets 8,4,2,1 stay inside the half)
__device__ __forceinline__ float halfAllSum(float v) {
#pragma unroll
    for (int o = 8; o; o >>= 1) v += __shfl_xor_sync(0xffffffffu, v, o);
    return v;
}

// ---------------------------------------------------------------------------
// logmap0: warp per node, lane handles dims [2l,2l+1].  weight -> bufA
// ---------------------------------------------------------------------------
__global__ void k_logmap(const float* __restrict__ w, int N) {
    int warp = (blockIdx.x * blockDim.x + threadIdx.x) >> 5;
    int lane = threadIdx.x & 31;
    if (warp >= N) return;
    const float2 v = *(const float2*)(w + (size_t)warp * DIM + lane * 2);
    float y0 = (lane == 0) ? 0.0f : v.x;
    float y1 = v.y;
    float n2 = warpAllSum(y0 * y0 + y1 * y1);
    float norm = fmaxf(sqrtf(n2), 1e-15f);
    float w0 = __shfl_sync(0xffffffffu, v.x, 0);
    float theta = fmaxf(w0, 1.0f + 1e-7f);
    float s = acoshf(theta) / norm;
    float2 o2;
    o2.x = (lane == 0) ? 0.0f : v.x * s;
    o2.y = v.y * s;
    *(float2*)(g_bufA + (size_t)warp * DIM + lane * 2) = o2;
}

// ---------------------------------------------------------------------------
// rowptr[r] = lower_bound(adj_row, r); rowptr[N] = E
// ---------------------------------------------------------------------------
__global__ void k_rowptr(const int* __restrict__ row, int E, int N) {
    int r = blockIdx.x * blockDim.x + threadIdx.x;
    if (r > N) return;
    int lo = 0, hi = E;
    while (lo < hi) {
        int m = (lo + hi) >> 1;
        if (__ldg(&row[m]) < r) lo = m + 1; else hi = m;
    }
    g_rowptr[r] = lo;
}

// ---------------------------------------------------------------------------
// Row gather, HALF-WARP PER ROW, lane owns dims [4q..4q+3].
// SOFTWARE-PIPELINED: next iteration's col/vals are prefetched BEFORE the
// current gathers issue, so the col-load latency hides under the previous
// gather. Odd tail handled branch-free: clamped index + zero weight.
// ---------------------------------------------------------------------------
__device__ __forceinline__ float4 half_row_gather(const float* __restrict__ in,
                                                  const float* __restrict__ vals,
                                                  const int* __restrict__ col,
                                                  int s, int e) {
    float4 sum = make_float4(0.0f, 0.0f, 0.0f, 0.0f);
    if (s >= e) return sum;
    int last = e - 1;
    int k = s;
    int k1 = min(k + 1, last);
    int   pc0 = __ldg(&col[k]);
    int   pc1 = __ldg(&col[k1]);
    float pv0 = __ldg(&vals[k]);
    float pv1 = (k + 1 <= last) ? __ldg(&vals[k1]) : 0.0f;
    while (true) {
        int   c0 = pc0, c1 = pc1;
        float v0 = pv0, v1 = pv1;
        k += 2;
        bool more = (k <= last);
        if (more) {
            int kk1 = min(k + 1, last);
            pc0 = __ldg(&col[k]);
            pc1 = __ldg(&col[kk1]);
            pv0 = __ldg(&vals[k]);
            pv1 = (k + 1 <= last) ? __ldg(&vals[kk1]) : 0.0f;
        }
        float4 x0 = *(const float4*)(in + (size_t)c0 * DIM);
        float4 x1 = *(const float4*)(in + (size_t)c1 * DIM);
        sum.x = fmaf(v0, x0.x, sum.x); sum.y = fmaf(v0, x0.y, sum.y);
        sum.z = fmaf(v0, x0.z, sum.z); sum.w = fmaf(v0, x0.w, sum.w);
        sum.x = fmaf(v1, x1.x, sum.x); sum.y = fmaf(v1, x1.y, sum.y);
        sum.z = fmaf(v1, x1.z, sum.z); sum.w = fmaf(v1, x1.w, sum.w);
        if (!more) break;
    }
    return sum;
}

// ---------------------------------------------------------------------------
// SpMV layers 1 & 2: warp handles rows {2w, 2w+1} (one per half).
// __launch_bounds__(256, 6): regs <= 40, 1536 thr/SM (75% occ) w/o spills.
// srcIsB: 0 -> read bufA write bufB ; 1 -> read bufB write bufA
// ---------------------------------------------------------------------------
__global__ void __launch_bounds__(256, 6)
k_spmv(const float* __restrict__ vals, const int* __restrict__ col,
       int N, int srcIsB) {
    int warp = (blockIdx.x * blockDim.x + threadIdx.x) >> 5;
    int lane = threadIdx.x & 31;
    int half = lane >> 4, q = lane & 15;
    int row = warp * 2 + half;
    bool valid = row < N;
    int rc = valid ? row : (N - 1);
    const float* __restrict__ in = (srcIsB ? g_bufB : g_bufA) + q * 4;
    float* __restrict__ out      = srcIsB ? g_bufA : g_bufB;
    int s = __ldg(&g_rowptr[rc]);
    int e = valid ? __ldg(&g_rowptr[rc + 1]) : s;
    float4 sum = half_row_gather(in, vals, col, s, e);
    if (valid)
        *(float4*)(out + (size_t)rc * DIM + q * 4) = sum;
}

// ---------------------------------------------------------------------------
// Fused layer 3 + expmap0 + proj: warp handles rows {2w, 2w+1}.
//   h3 = A*h2 (gather bufA); acc = (h1+h2)+h3; final h -> bufB[row]
// ---------------------------------------------------------------------------
__global__ void __launch_bounds__(256, 6)
k_spmv3_final(const float* __restrict__ vals, const int* __restrict__ col, int N) {
    int warp = (blockIdx.x * blockDim.x + threadIdx.x) >> 5;
    int lane = threadIdx.x & 31;
    int half = lane >> 4, q = lane & 15;
    int row = warp * 2 + half;
    bool valid = row < N;
    int rc = valid ? row : (N - 1);
    int s = __ldg(&g_rowptr[rc]);
    int e = valid ? __ldg(&g_rowptr[rc + 1]) : s;

    float4 h3 = half_row_gather(g_bufA + q * 4, vals, col, s, e);

    size_t off = (size_t)rc * DIM + q * 4;
    const float4 h1 = *(const float4*)(g_bufB + off);
    const float4 h2 = *(const float4*)(g_bufA + off);
    float ax = (h1.x + h2.x) + h3.x;
    float ay = (h1.y + h2.y) + h3.y;
    float az = (h1.z + h2.z) + h3.z;
    float aw = (h1.w + h2.w) + h3.w;

    float x0 = (q == 0) ? 0.0f : ax;   // dim0 = x of q==0
    float n2 = halfAllSum(x0 * x0 + ay * ay + az * az + aw * aw);
    float xn = fmaxf(sqrtf(n2), 1e-15f);
    float sc = sinhf(xn) / xn;
    float r0 = x0 * sc, r1 = ay * sc, r2 = az * sc, r3 = aw * sc;
    float rn2 = halfAllSum(r0 * r0 + r1 * r1 + r2 * r2 + r3 * r3);
    float first = sqrtf(1.0f + rn2);
    if (valid) {
        float4 o;
        o.x = (q == 0) ? first : r0;
        o.y = r1; o.z = r2; o.w = r3;
        *(float4*)(g_bufB + off) = o;
    }
}

__global__ void k_zero(float* out, int n) {
    int i = blockIdx.x * blockDim.x + threadIdx.x;
    if (i < n) out[i] = 0.0f;
}

// ---------------------------------------------------------------------------
// loss: one warp per training pair; reads final embeddings from bufB.
// ---------------------------------------------------------------------------
__global__ void k_loss(const int* __restrict__ anchor, const int* __restrict__ pos,
                       const int* __restrict__ neg, int M, int numNeg,
                       float* __restrict__ out) {
    int lane = threadIdx.x & 31;
    int wib  = threadIdx.x >> 5;
    int warp = blockIdx.x * (blockDim.x >> 5) + wib;
    __shared__ float partial[8];

    float contrib = 0.0f;
    if (warp < M) {
        const float* __restrict__ h = g_bufB;
        int ai = __ldg(&anchor[warp]);
        int pi = __ldg(&pos[warp]);
        float2 av = *(const float2*)(h + (size_t)ai * DIM + lane * 2);
        float2 pv = *(const float2*)(h + (size_t)pi * DIM + lane * 2);
        float dotap = warpAllSum(av.x * pv.x + av.y * pv.y);
        float a0 = __shfl_sync(0xffffffffu, av.x, 0);
        float p0 = __shfl_sync(0xffffffffu, pv.x, 0);
        float mink = dotap - 2.0f * a0 * p0;
        float th   = fmaxf(-mink, 1.0f + 1e-7f);
        float ac   = acoshf(th);
        float pos_score = fminf(ac * ac, 50.0f);

        float score = (1.0f - mink - a0 - p0) / (a0 * p0);
        float w = 1.0f / (1.0f + expf(score));   // sigmoid(-score)

        // hard negative: argmin_j ||h[neg_j] - p||^2 (first min kept)
        float best = 3.4e38f;
        float2 bv = make_float2(0.0f, 0.0f);
        if (numNeg == 16) {
#pragma unroll 4
            for (int j = 0; j < 16; j++) {
                int ni = __ldg(&neg[(size_t)warp * 16 + j]);
                float2 nv = *(const float2*)(h + (size_t)ni * DIM + lane * 2);
                float dx = nv.x - pv.x, dy = nv.y - pv.y;
                float d = warpAllSum(dx * dx + dy * dy);
                if (d < best) { best = d; bv = nv; }
            }
        } else {
            for (int j = 0; j < numNeg; j++) {
                int ni = __ldg(&neg[(size_t)warp * numNeg + j]);
                float2 nv = *(const float2*)(h + (size_t)ni * DIM + lane * 2);
                float dx = nv.x - pv.x, dy = nv.y - pv.y;
                float d = warpAllSum(dx * dx + dy * dy);
                if (d < best) { best = d; bv = nv; }
            }
        }
        float dotan = warpAllSum(av.x * bv.x + av.y * bv.y);
        float n0 = __shfl_sync(0xffffffffu, bv.x, 0);
        float minkn = dotan - 2.0f * a0 * n0;
        float thn = fmaxf(-minkn, 1.0f + 1e-7f);
        float acn = acoshf(thn);
        float neg_score = fminf(acn * acn, 50.0f);

        contrib = fmaxf(pos_score - neg_score + 0.1f * w, 0.0f);
    }
    if (lane == 0) partial[wib] = contrib;
    __syncthreads();
    if (threadIdx.x == 0) {
        float s = 0.0f;
#pragma unroll
        for (int i = 0; i < 8; i++) s += partial[i];
        atomicAdd(out, s);
    }
}

// ---------------------------------------------------------------------------
extern "C" void kernel_launch(void* const* d_in, const int* in_sizes, int n_in,
                              void* d_out, int out_size) {
    const float* weight   = (const float*)d_in[0];
    const float* adj_vals = (const float*)d_in[1];
    const int*   adj_row  = (const int*)d_in[2];
    const int*   adj_col  = (const int*)d_in[3];
    const int*   anchor   = (const int*)d_in[4];
    const int*   pos      = (const int*)d_in[5];
    const int*   neg      = (const int*)d_in[6];
    float* out = (float*)d_out;

    int N = in_sizes[0] / DIM;         // 200000
    int E = in_sizes[1];               // 1.6M
    int M = in_sizes[4];               // 65536
    int numNeg = (M > 0) ? in_sizes[6] / M : 16;

    const int TPB = 256;               // 8 warps per block
    int logBlocks  = (N + 7) / 8;              // warp per node
    int spmvWarps  = (N + 1) / 2;              // warp per 2 rows
    int spmvBlocks = (spmvWarps + 7) / 8;
    int rpBlocks   = (N + 1 + TPB - 1) / TPB;
    int lossBlocks = (M + 7) / 8;

    k_logmap<<<logBlocks, TPB>>>(weight, N);
    k_rowptr<<<rpBlocks, TPB>>>(adj_row, E, N);
    k_spmv<<<spmvBlocks, TPB>>>(adj_vals, adj_col, N, /*srcIsB=*/0); // A(x_t) -> B(h1)
    k_spmv<<<spmvBlocks, TPB>>>(adj_vals, adj_col, N, /*srcIsB=*/1); // B(h1) -> A(h2)
    k_spmv3_final<<<spmvBlocks, TPB>>>(adj_vals, adj_col, N);        // -> B(final h)
    k_zero<<<(out_size + TPB - 1) / TPB, TPB>>>(out, out_size);
    k_loss<<<lossBlocks, TPB>>>(anchor, pos, neg, M, numNeg, out);
}

// round 14
// speedup vs baseline: 1.2856x; 1.2856x over previous
#include <cuda_runtime.h>
#include <math.h>

#define DIM 64
#define MAXN 200000

// Scratch (allocation-free rule: __device__ globals). 102 MB total.
__device__ float g_bufA[(size_t)MAXN * DIM];
__device__ float g_bufB[(size_t)MAXN * DIM];
__device__ int   g_rowptr[MAXN + 1];

__device__ __forceinline__ float warpAllSum(float v) {
#pragma unroll
    for (int o = 16; o; o >>= 1) v += __shfl_xor_sync(0xffffffffu, v, o);
    return v;
}

// butterfly within a 16-lane half (offsets 8,4,2,1 stay inside the half)
__device__ __forceinline__ float halfAllSum(float v) {
#pragma unroll
    for (int o = 8; o; o >>= 1) v += __shfl_xor_sync(0xffffffffu, v, o);
    return v;
}

// ---------------------------------------------------------------------------
// logmap0: warp per node, lane handles dims [2l,2l+1].  weight -> bufA
// ---------------------------------------------------------------------------
__global__ void k_logmap(const float* __restrict__ w, int N) {
    int warp = (blockIdx.x * blockDim.x + threadIdx.x) >> 5;
    int lane = threadIdx.x & 31;
    if (warp >= N) return;
    const float2 v = *(const float2*)(w + (size_t)warp * DIM + lane * 2);
    float y0 = (lane == 0) ? 0.0f : v.x;
    float y1 = v.y;
    float n2 = warpAllSum(y0 * y0 + y1 * y1);
    float norm = fmaxf(sqrtf(n2), 1e-15f);
    float w0 = __shfl_sync(0xffffffffu, v.x, 0);
    float theta = fmaxf(w0, 1.0f + 1e-7f);
    float s = acoshf(theta) / norm;
    float2 o2;
    o2.x = (lane == 0) ? 0.0f : v.x * s;
    o2.y = v.y * s;
    *(float2*)(g_bufA + (size_t)warp * DIM + lane * 2) = o2;
}

// ---------------------------------------------------------------------------
// rowptr[r] = lower_bound(adj_row, r); rowptr[N] = E.  Also zeroes d_out.
// ---------------------------------------------------------------------------
__global__ void k_rowptr(const int* __restrict__ row, int E, int N,
                         float* __restrict__ out, int out_size) {
    int r = blockIdx.x * blockDim.x + threadIdx.x;
    if (r < out_size) out[r] = 0.0f;
    if (r > N) return;
    int lo = 0, hi = E;
    while (lo < hi) {
        int m = (lo + hi) >> 1;
        if (__ldg(&row[m]) < r) lo = m + 1; else hi = m;
    }
    g_rowptr[r] = lo;
}

// ---------------------------------------------------------------------------
// Row gather, HALF-WARP PER ROW, lane owns dims [4q..4q+3]. No reduction.
// 2-edge unroll -> 2 gathers in flight per half; one LDG serves both halves.
// ---------------------------------------------------------------------------
__device__ __forceinline__ float4 half_row_gather(const float* __restrict__ in,
                                                  const float* __restrict__ vals,
                                                  const int* __restrict__ col,
                                                  int s, int e) {
    float4 sum = make_float4(0.0f, 0.0f, 0.0f, 0.0f);
    int k = s;
    for (; k + 2 <= e; k += 2) {
        int   c0 = __ldg(&col[k]);
        int   c1 = __ldg(&col[k + 1]);
        float v0 = __ldg(&vals[k]);
        float v1 = __ldg(&vals[k + 1]);
        float4 x0 = *(const float4*)(in + (size_t)c0 * DIM);
        float4 x1 = *(const float4*)(in + (size_t)c1 * DIM);
        sum.x = fmaf(v0, x0.x, sum.x); sum.y = fmaf(v0, x0.y, sum.y);
        sum.z = fmaf(v0, x0.z, sum.z); sum.w = fmaf(v0, x0.w, sum.w);
        sum.x = fmaf(v1, x1.x, sum.x); sum.y = fmaf(v1, x1.y, sum.y);
        sum.z = fmaf(v1, x1.z, sum.z); sum.w = fmaf(v1, x1.w, sum.w);
    }
    if (k < e) {
        int   c = __ldg(&col[k]);
        float v = __ldg(&vals[k]);
        float4 x = *(const float4*)(in + (size_t)c * DIM);
        sum.x = fmaf(v, x.x, sum.x); sum.y = fmaf(v, x.y, sum.y);
        sum.z = fmaf(v, x.z, sum.z); sum.w = fmaf(v, x.w, sum.w);
    }
    return sum;
}

// ---------------------------------------------------------------------------
// SpMV layers 1 & 2: warp handles rows {2w, 2w+1} (one per half).
// __launch_bounds__(256, 8): cap regs at 32 -> 2048 threads/SM resident.
// srcIsB: 0 -> read bufA write bufB ; 1 -> read bufB write bufA
// ---------------------------------------------------------------------------
__global__ void __launch_bounds__(256, 8)
k_spmv(const float* __restrict__ vals, const int* __restrict__ col,
       int N, int srcIsB) {
    int warp = (blockIdx.x * blockDim.x + threadIdx.x) >> 5;
    int lane = threadIdx.x & 31;
    int half = lane >> 4, q = lane & 15;
    int row = warp * 2 + half;
    bool valid = row < N;
    int rc = valid ? row : (N - 1);
    const float* __restrict__ in = (srcIsB ? g_bufB : g_bufA) + q * 4;
    float* __restrict__ out      = srcIsB ? g_bufA : g_bufB;
    int s = __ldg(&g_rowptr[rc]);
    int e = valid ? __ldg(&g_rowptr[rc + 1]) : s;
    float4 sum = half_row_gather(in, vals, col, s, e);
    if (valid)
        *(float4*)(out + (size_t)rc * DIM + q * 4) = sum;
}

// ---------------------------------------------------------------------------
// Fused layer 3 + expmap0 + proj: warp handles rows {2w, 2w+1}.
//   h3 = A*h2 (gather bufA); acc = (h1+h2)+h3; final h -> bufB[row]
// ---------------------------------------------------------------------------
__global__ void __launch_bounds__(256, 8)
k_spmv3_final(const float* __restrict__ vals, const int* __restrict__ col, int N) {
    int warp = (blockIdx.x * blockDim.x + threadIdx.x) >> 5;
    int lane = threadIdx.x & 31;
    int half = lane >> 4, q = lane & 15;
    int row = warp * 2 + half;
    bool valid = row < N;
    int rc = valid ? row : (N - 1);
    int s = __ldg(&g_rowptr[rc]);
    int e = valid ? __ldg(&g_rowptr[rc + 1]) : s;

    float4 h3 = half_row_gather(g_bufA + q * 4, vals, col, s, e);

    size_t off = (size_t)rc * DIM + q * 4;
    const float4 h1 = *(const float4*)(g_bufB + off);
    const float4 h2 = *(const float4*)(g_bufA + off);
    float ax = (h1.x + h2.x) + h3.x;
    float ay = (h1.y + h2.y) + h3.y;
    float az = (h1.z + h2.z) + h3.z;
    float aw = (h1.w + h2.w) + h3.w;

    float x0 = (q == 0) ? 0.0f : ax;   // dim0 = x of q==0
    float n2 = halfAllSum(x0 * x0 + ay * ay + az * az + aw * aw);
    float xn = fmaxf(sqrtf(n2), 1e-15f);
    float sc = sinhf(xn) / xn;
    float r0 = x0 * sc, r1 = ay * sc, r2 = az * sc, r3 = aw * sc;
    float rn2 = halfAllSum(r0 * r0 + r1 * r1 + r2 * r2 + r3 * r3);
    float first = sqrtf(1.0f + rn2);
    if (valid) {
        float4 o;
        o.x = (q == 0) ? first : r0;
        o.y = r1; o.z = r2; o.w = r3;
        *(float4*)(g_bufB + off) = o;
    }
}

// ---------------------------------------------------------------------------
// loss: HALF-WARP PER PAIR, lane q owns dims [4q..4q+3] (float4).
// One gather instruction serves both halves; 4-shfl reductions.
// ---------------------------------------------------------------------------
__global__ void __launch_bounds__(256, 8)
k_loss(const int* __restrict__ anchor, const int* __restrict__ pos,
       const int* __restrict__ neg, int M, int numNeg,
       float* __restrict__ out) {
    int tid  = threadIdx.x;
    int lane = tid & 31;
    int wib  = tid >> 5;
    int half = lane >> 4, q = lane & 15;
    int base = half << 4;
    int warp = blockIdx.x * 8 + wib;
    int m = warp * 2 + half;
    __shared__ float partial[8];

    float contrib = 0.0f;
    if (m < M) {
        const float* __restrict__ h = g_bufB + q * 4;
        int ai = __ldg(&anchor[m]);
        int pi = __ldg(&pos[m]);
        float4 av = *(const float4*)(h + (size_t)ai * DIM);
        float4 pv = *(const float4*)(h + (size_t)pi * DIM);
        float dotap = halfAllSum(av.x * pv.x + av.y * pv.y + av.z * pv.z + av.w * pv.w);
        float a0 = __shfl_sync(0xffffffffu, av.x, base);  // dim0 lives in q==0 .x
        float p0 = __shfl_sync(0xffffffffu, pv.x, base);
        float mink = dotap - 2.0f * a0 * p0;
        float th   = fmaxf(-mink, 1.0f + 1e-7f);
        float ac   = acoshf(th);
        float pos_score = fminf(ac * ac, 50.0f);

        float score = (1.0f - mink - a0 - p0) / (a0 * p0);
        float w = 1.0f / (1.0f + expf(score));   // sigmoid(-score)

        // hard negative: argmin_j ||h[neg_j] - p||^2 (first min kept)
        float best = 3.4e38f;
        float4 bv = make_float4(0.0f, 0.0f, 0.0f, 0.0f);
        const int* nrow = neg + (size_t)m * numNeg;
        if (numNeg == 16) {
#pragma unroll 4
            for (int j = 0; j < 16; j++) {
                int ni = __ldg(&nrow[j]);
                float4 nv = *(const float4*)(h + (size_t)ni * DIM);
                float dx = nv.x - pv.x, dy = nv.y - pv.y;
                float dz = nv.z - pv.z, dw = nv.w - pv.w;
                float d = halfAllSum(dx * dx + dy * dy + dz * dz + dw * dw);
                if (d < best) { best = d; bv = nv; }
            }
        } else {
            for (int j = 0; j < numNeg; j++) {
                int ni = __ldg(&nrow[j]);
                float4 nv = *(const float4*)(h + (size_t)ni * DIM);
                float dx = nv.x - pv.x, dy = nv.y - pv.y;
                float dz = nv.z - pv.z, dw = nv.w - pv.w;
                float d = halfAllSum(dx * dx + dy * dy + dz * dz + dw * dw);
                if (d < best) { best = d; bv = nv; }
            }
        }
        float dotan = halfAllSum(av.x * bv.x + av.y * bv.y + av.z * bv.z + av.w * bv.w);
        float n0 = __shfl_sync(0xffffffffu, bv.x, base);
        float minkn = dotan - 2.0f * a0 * n0;
        float thn = fmaxf(-minkn, 1.0f + 1e-7f);
        float acn = acoshf(thn);
        float neg_score = fminf(acn * acn, 50.0f);

        contrib = fmaxf(pos_score - neg_score + 0.1f * w, 0.0f);
    }
    // lane 0 of each half holds its pair's contrib; fold halves, then block.
    contrib += __shfl_xor_sync(0xffffffffu, contrib, 16);  // lanes 0 & 16 combine
    if (lane == 0) partial[wib] = contrib;
    __syncthreads();
    if (tid == 0) {
        float s = 0.0f;
#pragma unroll
        for (int i = 0; i < 8; i++) s += partial[i];
        atomicAdd(out, s);
    }
}

// ---------------------------------------------------------------------------
extern "C" void kernel_launch(void* const* d_in, const int* in_sizes, int n_in,
                              void* d_out, int out_size) {
    const float* weight   = (const float*)d_in[0];
    const float* adj_vals = (const float*)d_in[1];
    const int*   adj_row  = (const int*)d_in[2];
    const int*   adj_col  = (const int*)d_in[3];
    const int*   anchor   = (const int*)d_in[4];
    const int*   pos      = (const int*)d_in[5];
    const int*   neg      = (const int*)d_in[6];
    float* out = (float*)d_out;

    int N = in_sizes[0] / DIM;         // 200000
    int E = in_sizes[1];               // 1.6M
    int M = in_sizes[4];               // 65536
    int numNeg = (M > 0) ? in_sizes[6] / M : 16;

    const int TPB = 256;               // 8 warps per block
    int logBlocks  = (N + 7) / 8;              // warp per node
    int spmvWarps  = (N + 1) / 2;              // warp per 2 rows
    int spmvBlocks = (spmvWarps + 7) / 8;
    int rpBlocks   = (N + 1 + TPB - 1) / TPB;
    int lossWarps  = (M + 1) / 2;              // warp per 2 pairs
    int lossBlocks = (lossWarps + 7) / 8;

    k_logmap<<<logBlocks, TPB>>>(weight, N);
    k_rowptr<<<rpBlocks, TPB>>>(adj_row, E, N, out, out_size);
    k_spmv<<<spmvBlocks, TPB>>>(adj_vals, adj_col, N, /*srcIsB=*/0); // A(x_t) -> B(h1)
    k_spmv<<<spmvBlocks, TPB>>>(adj_vals, adj_col, N, /*srcIsB=*/1); // B(h1) -> A(h2)
    k_spmv3_final<<<spmvBlocks, TPB>>>(adj_vals, adj_col, N);        // -> B(final h)
    k_loss<<<lossBlocks, TPB>>>(anchor, pos, neg, M, numNeg, out);
}

// round 15
// speedup vs baseline: 1.3127x; 1.0210x over previous
#include <cuda_runtime.h>
#include <math.h>

#define DIM 64
#define MAXN 200000
#define MAXE 1600000

// Scratch (allocation-free rule: __device__ globals).
__device__ float  g_bufA[(size_t)MAXN * DIM];
__device__ float  g_bufB[(size_t)MAXN * DIM];
__device__ float2 g_edge[MAXE];          // packed (col-as-float-bits, val)
__device__ int    g_rowptr[MAXN + 1];

__device__ __forceinline__ float warpAllSum(float v) {
#pragma unroll
    for (int o = 16; o; o >>= 1) v += __shfl_xor_sync(0xffffffffu, v, o);
    return v;
}

// butterfly within a 16-lane half (offsets 8,4,2,1 stay inside the half)
__device__ __forceinline__ float halfAllSum(float v) {
#pragma unroll
    for (int o = 8; o; o >>= 1) v += __shfl_xor_sync(0xffffffffu, v, o);
    return v;
}

// ---------------------------------------------------------------------------
// Fused prep: blocks [0, logBlocks) run logmap0 (warp per node, weight->bufA);
// blocks [logBlocks, ...) pack edges, build rowptr, zero the output.
// ---------------------------------------------------------------------------
__global__ void k_prep(const float* __restrict__ w,
                       const int* __restrict__ row, const int* __restrict__ col,
                       const float* __restrict__ vals,
                       int N, int E, int logBlocks,
                       float* __restrict__ out, int out_size) {
    if ((int)blockIdx.x < logBlocks) {
        // ---- logmap0 ----
        int warp = (blockIdx.x * blockDim.x + threadIdx.x) >> 5;
        int lane = threadIdx.x & 31;
        if (warp >= N) return;
        const float2 v = *(const float2*)(w + (size_t)warp * DIM + lane * 2);
        float y0 = (lane == 0) ? 0.0f : v.x;
        float y1 = v.y;
        float n2 = warpAllSum(y0 * y0 + y1 * y1);
        float norm = fmaxf(sqrtf(n2), 1e-15f);
        float w0 = __shfl_sync(0xffffffffu, v.x, 0);
        float theta = fmaxf(w0, 1.0f + 1e-7f);
        float s = acoshf(theta) / norm;
        float2 o2;
        o2.x = (lane == 0) ? 0.0f : v.x * s;
        o2.y = v.y * s;
        *(float2*)(g_bufA + (size_t)warp * DIM + lane * 2) = o2;
    } else {
        int i = (blockIdx.x - logBlocks) * blockDim.x + threadIdx.x;
        if (i < out_size) out[i] = 0.0f;
        if (i < E) {
            float2 p;
            p.x = __int_as_float(__ldg(&col[i]));
            p.y = __ldg(&vals[i]);
            g_edge[i] = p;
        }
        if (i <= N) {
            int lo = 0, hi = E;
            while (lo < hi) {
                int m = (lo + hi) >> 1;
                if (__ldg(&row[m]) < i) lo = m + 1; else hi = m;
            }
            g_rowptr[i] = lo;
        }
    }
}

// ---------------------------------------------------------------------------
// Row gather, HALF-WARP PER ROW, lane owns dims [4q..4q+3]. No reduction.
// Packed edge loads: ONE LDG.64 per edge. 2-edge unroll.
// ---------------------------------------------------------------------------
__device__ __forceinline__ float4 half_row_gather(const float* __restrict__ in,
                                                  int s, int e) {
    float4 sum = make_float4(0.0f, 0.0f, 0.0f, 0.0f);
    int k = s;
    for (; k + 2 <= e; k += 2) {
        float2 p0 = __ldg(&g_edge[k]);
        float2 p1 = __ldg(&g_edge[k + 1]);
        int   c0 = __float_as_int(p0.x);
        int   c1 = __float_as_int(p1.x);
        float v0 = p0.y, v1 = p1.y;
        float4 x0 = *(const float4*)(in + (size_t)c0 * DIM);
        float4 x1 = *(const float4*)(in + (size_t)c1 * DIM);
        sum.x = fmaf(v0, x0.x, sum.x); sum.y = fmaf(v0, x0.y, sum.y);
        sum.z = fmaf(v0, x0.z, sum.z); sum.w = fmaf(v0, x0.w, sum.w);
        sum.x = fmaf(v1, x1.x, sum.x); sum.y = fmaf(v1, x1.y, sum.y);
        sum.z = fmaf(v1, x1.z, sum.z); sum.w = fmaf(v1, x1.w, sum.w);
    }
    if (k < e) {
        float2 p = __ldg(&g_edge[k]);
        int   c = __float_as_int(p.x);
        float v = p.y;
        float4 x = *(const float4*)(in + (size_t)c * DIM);
        sum.x = fmaf(v, x.x, sum.x); sum.y = fmaf(v, x.y, sum.y);
        sum.z = fmaf(v, x.z, sum.z); sum.w = fmaf(v, x.w, sum.w);
    }
    return sum;
}

// ---------------------------------------------------------------------------
// SpMV layers 1 & 2: warp handles rows {2w, 2w+1} (one per half).
// __launch_bounds__(256, 8): cap regs at 32 -> 2048 threads/SM resident.
// srcIsB: 0 -> read bufA write bufB ; 1 -> read bufB write bufA
// ---------------------------------------------------------------------------
__global__ void __launch_bounds__(256, 8)
k_spmv(int N, int srcIsB) {
    int warp = (blockIdx.x * blockDim.x + threadIdx.x) >> 5;
    int lane = threadIdx.x & 31;
    int half = lane >> 4, q = lane & 15;
    int row = warp * 2 + half;
    bool valid = row < N;
    int rc = valid ? row : (N - 1);
    const float* __restrict__ in = (srcIsB ? g_bufB : g_bufA) + q * 4;
    float* __restrict__ out      = srcIsB ? g_bufA : g_bufB;
    int s = __ldg(&g_rowptr[rc]);
    int e = valid ? __ldg(&g_rowptr[rc + 1]) : s;
    float4 sum = half_row_gather(in, s, e);
    if (valid)
        *(float4*)(out + (size_t)rc * DIM + q * 4) = sum;
}

// ---------------------------------------------------------------------------
// Fused layer 3 + expmap0 + proj: warp handles rows {2w, 2w+1}.
//   h3 = A*h2 (gather bufA); acc = (h1+h2)+h3; final h -> bufB[row]
// ---------------------------------------------------------------------------
__global__ void __launch_bounds__(256, 8)
k_spmv3_final(int N) {
    int warp = (blockIdx.x * blockDim.x + threadIdx.x) >> 5;
    int lane = threadIdx.x & 31;
    int half = lane >> 4, q = lane & 15;
    int row = warp * 2 + half;
    bool valid = row < N;
    int rc = valid ? row : (N - 1);
    int s = __ldg(&g_rowptr[rc]);
    int e = valid ? __ldg(&g_rowptr[rc + 1]) : s;

    float4 h3 = half_row_gather(g_bufA + q * 4, s, e);

    size_t off = (size_t)rc * DIM + q * 4;
    const float4 h1 = *(const float4*)(g_bufB + off);
    const float4 h2 = *(const float4*)(g_bufA + off);
    float ax = (h1.x + h2.x) + h3.x;
    float ay = (h1.y + h2.y) + h3.y;
    float az = (h1.z + h2.z) + h3.z;
    float aw = (h1.w + h2.w) + h3.w;

    float x0 = (q == 0) ? 0.0f : ax;   // dim0 = x of q==0
    float n2 = halfAllSum(x0 * x0 + ay * ay + az * az + aw * aw);
    float xn = fmaxf(sqrtf(n2), 1e-15f);
    float sc = sinhf(xn) / xn;
    float r0 = x0 * sc, r1 = ay * sc, r2 = az * sc, r3 = aw * sc;
    float rn2 = halfAllSum(r0 * r0 + r1 * r1 + r2 * r2 + r3 * r3);
    float first = sqrtf(1.0f + rn2);
    if (valid) {
        float4 o;
        o.x = (q == 0) ? first : r0;
        o.y = r1; o.z = r2; o.w = r3;
        *(float4*)(g_bufB + off) = o;
    }
}

// ---------------------------------------------------------------------------
// loss: HALF-WARP PER PAIR, lane q owns dims [4q..4q+3] (float4).
// ---------------------------------------------------------------------------
__global__ void __launch_bounds__(256, 8)
k_loss(const int* __restrict__ anchor, const int* __restrict__ pos,
       const int* __restrict__ neg, int M, int numNeg,
       float* __restrict__ out) {
    int tid  = threadIdx.x;
    int lane = tid & 31;
    int wib  = tid >> 5;
    int half = lane >> 4, q = lane & 15;
    int base = half << 4;
    int warp = blockIdx.x * 8 + wib;
    int m = warp * 2 + half;
    __shared__ float partial[8];

    float contrib = 0.0f;
    if (m < M) {
        const float* __restrict__ h = g_bufB + q * 4;
        int ai = __ldg(&anchor[m]);
        int pi = __ldg(&pos[m]);
        float4 av = *(const float4*)(h + (size_t)ai * DIM);
        float4 pv = *(const float4*)(h + (size_t)pi * DIM);
        float dotap = halfAllSum(av.x * pv.x + av.y * pv.y + av.z * pv.z + av.w * pv.w);
        float a0 = __shfl_sync(0xffffffffu, av.x, base);  // dim0 lives in q==0 .x
        float p0 = __shfl_sync(0xffffffffu, pv.x, base);
        float mink = dotap - 2.0f * a0 * p0;
        float th   = fmaxf(-mink, 1.0f + 1e-7f);
        float ac   = acoshf(th);
        float pos_score = fminf(ac * ac, 50.0f);

        float score = (1.0f - mink - a0 - p0) / (a0 * p0);
        float w = 1.0f / (1.0f + expf(score));   // sigmoid(-score)

        // hard negative: argmin_j ||h[neg_j] - p||^2 (first min kept)
        float best = 3.4e38f;
        float4 bv = make_float4(0.0f, 0.0f, 0.0f, 0.0f);
        const int* nrow = neg + (size_t)m * numNeg;
        if (numNeg == 16) {
#pragma unroll 4
            for (int j = 0; j < 16; j++) {
                int ni = __ldg(&nrow[j]);
                float4 nv = *(const float4*)(h + (size_t)ni * DIM);
                float dx = nv.x - pv.x, dy = nv.y - pv.y;
                float dz = nv.z - pv.z, dw = nv.w - pv.w;
                float d = halfAllSum(dx * dx + dy * dy + dz * dz + dw * dw);
                if (d < best) { best = d; bv = nv; }
            }
        } else {
            for (int j = 0; j < numNeg; j++) {
                int ni = __ldg(&nrow[j]);
                float4 nv = *(const float4*)(h + (size_t)ni * DIM);
                float dx = nv.x - pv.x, dy = nv.y - pv.y;
                float dz = nv.z - pv.z, dw = nv.w - pv.w;
                float d = halfAllSum(dx * dx + dy * dy + dz * dz + dw * dw);
                if (d < best) { best = d; bv = nv; }
            }
        }
        float dotan = halfAllSum(av.x * bv.x + av.y * bv.y + av.z * bv.z + av.w * bv.w);
        float n0 = __shfl_sync(0xffffffffu, bv.x, base);
        float minkn = dotan - 2.0f * a0 * n0;
        float thn = fmaxf(-minkn, 1.0f + 1e-7f);
        float acn = acoshf(thn);
        float neg_score = fminf(acn * acn, 50.0f);

        contrib = fmaxf(pos_score - neg_score + 0.1f * w, 0.0f);
    }
    contrib += __shfl_xor_sync(0xffffffffu, contrib, 16);  // fold halves
    if (lane == 0) partial[wib] = contrib;
    __syncthreads();
    if (tid == 0) {
        float s = 0.0f;
#pragma unroll
        for (int i = 0; i < 8; i++) s += partial[i];
        atomicAdd(out, s);
    }
}

// ---------------------------------------------------------------------------
extern "C" void kernel_launch(void* const* d_in, const int* in_sizes, int n_in,
                              void* d_out, int out_size) {
    const float* weight   = (const float*)d_in[0];
    const float* adj_vals = (const float*)d_in[1];
    const int*   adj_row  = (const int*)d_in[2];
    const int*   adj_col  = (const int*)d_in[3];
    const int*   anchor   = (const int*)d_in[4];
    const int*   pos      = (const int*)d_in[5];
    const int*   neg      = (const int*)d_in[6];
    float* out = (float*)d_out;

    int N = in_sizes[0] / DIM;         // 200000
    int E = in_sizes[1];               // 1.6M
    int M = in_sizes[4];               // 65536
    int numNeg = (M > 0) ? in_sizes[6] / M : 16;

    const int TPB = 256;               // 8 warps per block
    int logBlocks  = (N + 7) / 8;      // warp per node (logmap part)
    int prepElems  = E;                // covers E, N+1, out_size
    if (prepElems < N + 1) prepElems = N + 1;
    if (prepElems < out_size) prepElems = out_size;
    int prepBlocks = logBlocks + (prepElems + TPB - 1) / TPB;
    int spmvWarps  = (N + 1) / 2;      // warp per 2 rows
    int spmvBlocks = (spmvWarps + 7) / 8;
    int lossWarps  = (M + 1) / 2;      // warp per 2 pairs
    int lossBlocks = (lossWarps + 7) / 8;

    k_prep<<<prepBlocks, TPB>>>(weight, adj_row, adj_col, adj_vals,
                                N, E, logBlocks, out, out_size);
    k_spmv<<<spmvBlocks, TPB>>>(N, /*srcIsB=*/0);   // A(x_t) -> B(h1)
    k_spmv<<<spmvBlocks, TPB>>>(N, /*srcIsB=*/1);   // B(h1) -> A(h2)
    k_spmv3_final<<<spmvBlocks, TPB>>>(N);          // -> B(final h)
    k_loss<<<lossBlocks, TPB>>>(anchor, pos, neg, M, numNeg, out);
}

// round 16
// speedup vs baseline: 1.3612x; 1.0370x over previous
#include <cuda_runtime.h>
#include <math.h>

#define DIM 64
#define MAXN 200000
#define MAXE 1600000

// Scratch (allocation-free rule: __device__ globals).
__device__ float  g_bufA[(size_t)MAXN * DIM];
__device__ float  g_bufB[(size_t)MAXN * DIM];
__device__ float2 g_edge[MAXE];          // packed (col-as-float-bits, val)
__device__ int    g_rowptr[MAXN + 1];

__device__ __forceinline__ float warpAllSum(float v) {
#pragma unroll
    for (int o = 16; o; o >>= 1) v += __shfl_xor_sync(0xffffffffu, v, o);
    return v;
}

// butterfly within a 16-lane half (offsets 8,4,2,1 stay inside the half)
__device__ __forceinline__ float halfAllSum(float v) {
#pragma unroll
    for (int o = 8; o; o >>= 1) v += __shfl_xor_sync(0xffffffffu, v, o);
    return v;
}

// ---------------------------------------------------------------------------
// Fused prep: blocks [0, logBlocks) run logmap0 (warp per node, weight->bufA);
// blocks [logBlocks, ...) pack edges, build rowptr, zero the output.
// ---------------------------------------------------------------------------
__global__ void k_prep(const float* __restrict__ w,
                       const int* __restrict__ row, const int* __restrict__ col,
                       const float* __restrict__ vals,
                       int N, int E, int logBlocks,
                       float* __restrict__ out, int out_size) {
    if ((int)blockIdx.x < logBlocks) {
        // ---- logmap0 ----
        int warp = (blockIdx.x * blockDim.x + threadIdx.x) >> 5;
        int lane = threadIdx.x & 31;
        if (warp >= N) return;
        const float2 v = *(const float2*)(w + (size_t)warp * DIM + lane * 2);
        float y0 = (lane == 0) ? 0.0f : v.x;
        float y1 = v.y;
        float n2 = warpAllSum(y0 * y0 + y1 * y1);
        float norm = fmaxf(sqrtf(n2), 1e-15f);
        float w0 = __shfl_sync(0xffffffffu, v.x, 0);
        float theta = fmaxf(w0, 1.0f + 1e-7f);
        float s = acoshf(theta) / norm;
        float2 o2;
        o2.x = (lane == 0) ? 0.0f : v.x * s;
        o2.y = v.y * s;
        *(float2*)(g_bufA + (size_t)warp * DIM + lane * 2) = o2;
    } else {
        int i = (blockIdx.x - logBlocks) * blockDim.x + threadIdx.x;
        if (i < out_size) out[i] = 0.0f;
        if (i < E) {
            float2 p;
            p.x = __int_as_float(__ldg(&col[i]));
            p.y = __ldg(&vals[i]);
            g_edge[i] = p;
        }
        if (i <= N) {
            int lo = 0, hi = E;
            while (lo < hi) {
                int m = (lo + hi) >> 1;
                if (__ldg(&row[m]) < i) lo = m + 1; else hi = m;
            }
            g_rowptr[i] = lo;
        }
    }
}

// ---------------------------------------------------------------------------
// Row gather, HALF-WARP PER ROW, lane owns dims [4q..4q+3]. No reduction.
// Packed edge loads: ONE LDG.64 per edge. 2-edge unroll.
// ---------------------------------------------------------------------------
__device__ __forceinline__ float4 half_row_gather(const float* __restrict__ in,
                                                  int s, int e) {
    float4 sum = make_float4(0.0f, 0.0f, 0.0f, 0.0f);
    int k = s;
    for (; k + 2 <= e; k += 2) {
        float2 p0 = __ldg(&g_edge[k]);
        float2 p1 = __ldg(&g_edge[k + 1]);
        int   c0 = __float_as_int(p0.x);
        int   c1 = __float_as_int(p1.x);
        float v0 = p0.y, v1 = p1.y;
        float4 x0 = *(const float4*)(in + (size_t)c0 * DIM);
        float4 x1 = *(const float4*)(in + (size_t)c1 * DIM);
        sum.x = fmaf(v0, x0.x, sum.x); sum.y = fmaf(v0, x0.y, sum.y);
        sum.z = fmaf(v0, x0.z, sum.z); sum.w = fmaf(v0, x0.w, sum.w);
        sum.x = fmaf(v1, x1.x, sum.x); sum.y = fmaf(v1, x1.y, sum.y);
        sum.z = fmaf(v1, x1.z, sum.z); sum.w = fmaf(v1, x1.w, sum.w);
    }
    if (k < e) {
        float2 p = __ldg(&g_edge[k]);
        int   c = __float_as_int(p.x);
        float v = p.y;
        float4 x = *(const float4*)(in + (size_t)c * DIM);
        sum.x = fmaf(v, x.x, sum.x); sum.y = fmaf(v, x.y, sum.y);
        sum.z = fmaf(v, x.z, sum.z); sum.w = fmaf(v, x.w, sum.w);
    }
    return sum;
}

// ---------------------------------------------------------------------------
// SpMV layers 1 & 2: warp handles rows {2w, 2w+1} (one per half).
// __launch_bounds__(256, 8): cap regs at 32 -> 2048 threads/SM resident.
// srcIsB: 0 -> read bufA write bufB ; 1 -> read bufB write bufA
// ---------------------------------------------------------------------------
__global__ void __launch_bounds__(256, 8)
k_spmv(int N, int srcIsB) {
    int warp = (blockIdx.x * blockDim.x + threadIdx.x) >> 5;
    int lane = threadIdx.x & 31;
    int half = lane >> 4, q = lane & 15;
    int row = warp * 2 + half;
    bool valid = row < N;
    int rc = valid ? row : (N - 1);
    const float* __restrict__ in = (srcIsB ? g_bufB : g_bufA) + q * 4;
    float* __restrict__ out      = srcIsB ? g_bufA : g_bufB;
    int s = __ldg(&g_rowptr[rc]);
    int e = valid ? __ldg(&g_rowptr[rc + 1]) : s;
    float4 sum = half_row_gather(in, s, e);
    if (valid)
        *(float4*)(out + (size_t)rc * DIM + q * 4) = sum;
}

// ---------------------------------------------------------------------------
// Fused layer 3 + expmap0 + proj: warp handles rows {2w, 2w+1}.
//   h3 = A*h2 (gather bufA); acc = (h1+h2)+h3; final h -> bufB[row]
// ---------------------------------------------------------------------------
__global__ void __launch_bounds__(256, 8)
k_spmv3_final(int N) {
    int warp = (blockIdx.x * blockDim.x + threadIdx.x) >> 5;
    int lane = threadIdx.x & 31;
    int half = lane >> 4, q = lane & 15;
    int row = warp * 2 + half;
    bool valid = row < N;
    int rc = valid ? row : (N - 1);
    int s = __ldg(&g_rowptr[rc]);
    int e = valid ? __ldg(&g_rowptr[rc + 1]) : s;

    float4 h3 = half_row_gather(g_bufA + q * 4, s, e);

    size_t off = (size_t)rc * DIM + q * 4;
    const float4 h1 = *(const float4*)(g_bufB + off);
    const float4 h2 = *(const float4*)(g_bufA + off);
    float ax = (h1.x + h2.x) + h3.x;
    float ay = (h1.y + h2.y) + h3.y;
    float az = (h1.z + h2.z) + h3.z;
    float aw = (h1.w + h2.w) + h3.w;

    float x0 = (q == 0) ? 0.0f : ax;   // dim0 = x of q==0
    float n2 = halfAllSum(x0 * x0 + ay * ay + az * az + aw * aw);
    float xn = fmaxf(sqrtf(n2), 1e-15f);
    float sc = sinhf(xn) / xn;
    float r0 = x0 * sc, r1 = ay * sc, r2 = az * sc, r3 = aw * sc;
    float rn2 = halfAllSum(r0 * r0 + r1 * r1 + r2 * r2 + r3 * r3);
    float first = sqrtf(1.0f + rn2);
    if (valid) {
        float4 o;
        o.x = (q == 0) ? first : r0;
        o.y = r1; o.z = r2; o.w = r3;
        *(float4*)(g_bufB + off) = o;
    }
}

// ---------------------------------------------------------------------------
// loss: HALF-WARP PER PAIR, lane q owns dims [4q..4q+3] (float4).
// Hard-negative argmin restructured: groups of 4 negatives with independent
// reduction chains (pipelined shuffles), scalar (best_d, best_j) tracking,
// single re-gather of the winning row. Strict < keeps first-min semantics.
// ---------------------------------------------------------------------------
__device__ __forceinline__ float neg_d2(const float* __restrict__ h, int ni,
                                        float4 pv) {
    float4 nv = *(const float4*)(h + (size_t)ni * DIM);
    float dx = nv.x - pv.x, dy = nv.y - pv.y;
    float dz = nv.z - pv.z, dw = nv.w - pv.w;
    return dx * dx + dy * dy + dz * dz + dw * dw;
}

__global__ void __launch_bounds__(256, 6)
k_loss(const int* __restrict__ anchor, const int* __restrict__ pos,
       const int* __restrict__ neg, int M, int numNeg,
       float* __restrict__ out) {
    int tid  = threadIdx.x;
    int lane = tid & 31;
    int wib  = tid >> 5;
    int half = lane >> 4, q = lane & 15;
    int base = half << 4;
    int warp = blockIdx.x * 8 + wib;
    int m = warp * 2 + half;
    __shared__ float partial[8];

    float contrib = 0.0f;
    if (m < M) {
        const float* __restrict__ h = g_bufB + q * 4;
        int ai = __ldg(&anchor[m]);
        int pi = __ldg(&pos[m]);
        float4 av = *(const float4*)(h + (size_t)ai * DIM);
        float4 pv = *(const float4*)(h + (size_t)pi * DIM);
        float dotap = halfAllSum(av.x * pv.x + av.y * pv.y + av.z * pv.z + av.w * pv.w);
        float a0 = __shfl_sync(0xffffffffu, av.x, base);  // dim0 lives in q==0 .x
        float p0 = __shfl_sync(0xffffffffu, pv.x, base);
        float mink = dotap - 2.0f * a0 * p0;
        float th   = fmaxf(-mink, 1.0f + 1e-7f);
        float ac   = acoshf(th);
        float pos_score = fminf(ac * ac, 50.0f);

        float score = (1.0f - mink - a0 - p0) / (a0 * p0);
        float w = 1.0f / (1.0f + expf(score));   // sigmoid(-score)

        // hard negative: argmin_j ||h[neg_j] - p||^2 (first min kept)
        const int* nrow = neg + (size_t)m * numNeg;
        float best = 3.4e38f;
        int bestj = 0;
        if (numNeg == 16) {
#pragma unroll
            for (int g = 0; g < 16; g += 4) {
                int n0 = __ldg(&nrow[g]);
                int n1 = __ldg(&nrow[g + 1]);
                int n2i = __ldg(&nrow[g + 2]);
                int n3 = __ldg(&nrow[g + 3]);
                float pd0 = neg_d2(h, n0, pv);
                float pd1 = neg_d2(h, n1, pv);
                float pd2 = neg_d2(h, n2i, pv);
                float pd3 = neg_d2(h, n3, pv);
                float d0 = halfAllSum(pd0);   // independent chains: pipeline
                float d1 = halfAllSum(pd1);
                float d2 = halfAllSum(pd2);
                float d3 = halfAllSum(pd3);
                if (d0 < best) { best = d0; bestj = g; }
                if (d1 < best) { best = d1; bestj = g + 1; }
                if (d2 < best) { best = d2; bestj = g + 2; }
                if (d3 < best) { best = d3; bestj = g + 3; }
            }
        } else {
            for (int j = 0; j < numNeg; j++) {
                float d = halfAllSum(neg_d2(h, __ldg(&nrow[j]), pv));
                if (d < best) { best = d; bestj = j; }
            }
        }
        int nb = __ldg(&nrow[bestj]);
        float4 bv = *(const float4*)(h + (size_t)nb * DIM);
        float dotan = halfAllSum(av.x * bv.x + av.y * bv.y + av.z * bv.z + av.w * bv.w);
        float n0f = __shfl_sync(0xffffffffu, bv.x, base);
        float minkn = dotan - 2.0f * a0 * n0f;
        float thn = fmaxf(-minkn, 1.0f + 1e-7f);
        float acn = acoshf(thn);
        float neg_score = fminf(acn * acn, 50.0f);

        contrib = fmaxf(pos_score - neg_score + 0.1f * w, 0.0f);
    }
    contrib += __shfl_xor_sync(0xffffffffu, contrib, 16);  // fold halves
    if (lane == 0) partial[wib] = contrib;
    __syncthreads();
    if (tid == 0) {
        float s = 0.0f;
#pragma unroll
        for (int i = 0; i < 8; i++) s += partial[i];
        atomicAdd(out, s);
    }
}

// ---------------------------------------------------------------------------
extern "C" void kernel_launch(void* const* d_in, const int* in_sizes, int n_in,
                              void* d_out, int out_size) {
    const float* weight   = (const float*)d_in[0];
    const float* adj_vals = (const float*)d_in[1];
    const int*   adj_row  = (const int*)d_in[2];
    const int*   adj_col  = (const int*)d_in[3];
    const int*   anchor   = (const int*)d_in[4];
    const int*   pos      = (const int*)d_in[5];
    const int*   neg      = (const int*)d_in[6];
    float* out = (float*)d_out;

    int N = in_sizes[0] / DIM;         // 200000
    int E = in_sizes[1];               // 1.6M
    int M = in_sizes[4];               // 65536
    int numNeg = (M > 0) ? in_sizes[6] / M : 16;

    const int TPB = 256;               // 8 warps per block
    int logBlocks  = (N + 7) / 8;      // warp per node (logmap part)
    int prepElems  = E;                // covers E, N+1, out_size
    if (prepElems < N + 1) prepElems = N + 1;
    if (prepElems < out_size) prepElems = out_size;
    int prepBlocks = logBlocks + (prepElems + TPB - 1) / TPB;
    int spmvWarps  = (N + 1) / 2;      // warp per 2 rows
    int spmvBlocks = (spmvWarps + 7) / 8;
    int lossWarps  = (M + 1) / 2;      // warp per 2 pairs
    int lossBlocks = (lossWarps + 7) / 8;

    k_prep<<<prepBlocks, TPB>>>(weight, adj_row, adj_col, adj_vals,
                                N, E, logBlocks, out, out_size);
    k_spmv<<<spmvBlocks, TPB>>>(N, /*srcIsB=*/0);   // A(x_t) -> B(h1)
    k_spmv<<<spmvBlocks, TPB>>>(N, /*srcIsB=*/1);   // B(h1) -> A(h2)
    k_spmv3_final<<<spmvBlocks, TPB>>>(N);          // -> B(final h)
    k_loss<<<lossBlocks, TPB>>>(anchor, pos, neg, M, numNeg, out);
}